// round 13
// baseline (speedup 1.0000x reference)
#include <cuda_runtime.h>

typedef unsigned long long ull;

#define TLEN 4000
#define HID  64
#define BT   2
#define NTHR 256

__device__ __forceinline__ void ffma2(ull &d, ull a, ull b) {
    asm("fma.rn.f32x2 %0, %1, %2, %0;" : "+l"(d) : "l"(a), "l"(b));
}
__device__ __forceinline__ float2 unpack2(ull v) {
    float2 r;
    asm("mov.b64 {%0, %1}, %2;" : "=f"(r.x), "=f"(r.y) : "l"(v));
    return r;
}
__device__ __forceinline__ ull pack2(float x, float y) {
    ull r;
    asm("mov.b64 %0, {%1, %2};" : "=l"(r) : "f"(x), "f"(y));
    return r;
}
__device__ __forceinline__ float tanha(float x) {
    float r;
    asm("tanh.approx.f32 %0, %1;" : "=f"(r) : "f"(x));
    return r;
}
__device__ __forceinline__ float fsigmoid(float x) {
    return fmaf(tanha(0.5f * x), 0.5f, 0.5f);
}

__global__ void __launch_bounds__(NTHR, 1)
lstm2_r13(const float* __restrict__ x,
          const float* __restrict__ W_ih0,
          const float* __restrict__ W_hh0,
          const float* __restrict__ b_ih0,
          const float* __restrict__ b_hh0,
          const float* __restrict__ W_ih1,
          const float* __restrict__ W_hh1,
          const float* __restrict__ b_ih1,
          const float* __restrict__ b_hh1,
          const float* __restrict__ W_fc,
          const float* __restrict__ b_fc,
          float* __restrict__ out)
{
    __shared__ __align__(16) float sh_x[BT * TLEN];       // 32 KB staged input
    __shared__ __align__(16) float sh_h[2][BT][2 * HID];  // dbl-buffered [h0|h1]
    __shared__ __align__(16) float sh_s[8][32][4];        // warp-local gate xchg

    const int tid   = threadIdx.x;
    const int w     = tid >> 5;
    const int l     = tid & 31;
    const int j     = l & 7;          // unit-local
    const int q     = l >> 3;         // gate index (i,f,g,o) AND pointwise combo
    const int u     = 8 * w + j;      // unit 0..63
    const int row   = q * HID + u;    // gate row this thread owns
    const int bbase = blockIdx.x * BT;
    const bool alt  = (w >= 4);       // SMSP partner phase: h1-block first

    // Stage x (two contiguous batch rows)
    {
        const float4* xg = (const float4*)(x + (size_t)bbase * TLEN);
        float4* xs = (float4*)sh_x;
        for (int i = tid; i < BT * TLEN / 4; i += NTHR) xs[i] = xg[i];
    }
    ((float2*)sh_h)[tid] = make_float2(0.0f, 0.0f);   // zero both slots (512 f)

    // Per-thread weight rows in registers (packed f32 pairs).
    ull wA[32], wI[32], wH[32];   // W_hh0 / W_ih1 / W_hh1 row `row`
    {
        const ulonglong2* p = (const ulonglong2*)(W_hh0 + row * HID);
        #pragma unroll
        for (int t = 0; t < 16; t++) { ulonglong2 v = p[t]; wA[2*t] = v.x; wA[2*t+1] = v.y; }
        p = (const ulonglong2*)(W_ih1 + row * HID);
        #pragma unroll
        for (int t = 0; t < 16; t++) { ulonglong2 v = p[t]; wI[2*t] = v.x; wI[2*t+1] = v.y; }
        p = (const ulonglong2*)(W_hh1 + row * HID);
        #pragma unroll
        for (int t = 0; t < 16; t++) { ulonglong2 v = p[t]; wH[2*t] = v.x; wH[2*t+1] = v.y; }
    }
    const float wx    = W_ih0[row];
    const float biasA = b_ih0[row] + b_hh0[row];
    const float biasB = b_ih1[row] + b_hh1[row];

    // Pointwise combo for this lane: q -> (layer Lq, batch bq), unit u.
    const int Lq = q >> 1;
    const int bq = q & 1;
    const int hoff = Lq * HID + u;
    float c = 0.0f;

    __syncthreads();

    // Iter k: matvec gA(k) [layer0 step k] + gB(k-1) [layer1 step k-1],
    // warp-local pointwise -> h0(k), h1(k-1). ONE CTA barrier per step.
    // Warps 0-3 and 4-7 traverse the two h-blocks in opposite order so the
    // two warps sharing each SMSP stall at different points.
    for (int k = 0; k <= TLEN; ++k) {
        const int rs = (k + 1) & 1;   // read slot  (= writes of iter k-1)
        const int ws = k & 1;         // write slot
        // ---- fused matvec ----
        {
            const int xk = (k < TLEN) ? k : TLEN - 1;
            const float xa = sh_x[xk];
            const float xb = sh_x[TLEN + xk];
            ull aA0x = pack2(fmaf(xa, wx, biasA), 0.0f), aA0y = pack2(0.0f, 0.0f);
            ull aA1x = pack2(fmaf(xb, wx, biasA), 0.0f), aA1y = pack2(0.0f, 0.0f);
            ull aB0x = pack2(biasB, 0.0f),               aB0y = pack2(0.0f, 0.0f);
            ull aB1x = aB0x,                             aB1y = pack2(0.0f, 0.0f);

            const ulonglong2* h0b0 = (const ulonglong2*)&sh_h[rs][0][0];
            const ulonglong2* h0b1 = (const ulonglong2*)&sh_h[rs][1][0];
            const ulonglong2* h1b0 = (const ulonglong2*)&sh_h[rs][0][HID];
            const ulonglong2* h1b1 = (const ulonglong2*)&sh_h[rs][1][HID];

            if (!alt) {
                #pragma unroll
                for (int t = 0; t < 16; t++) {        // h0 feeds wA and wI
                    ulonglong2 v0 = h0b0[t], v1 = h0b1[t];
                    ffma2(aA0x, wA[2*t],   v0.x);
                    ffma2(aA1x, wA[2*t],   v1.x);
                    ffma2(aB0x, wI[2*t],   v0.x);
                    ffma2(aB1x, wI[2*t],   v1.x);
                    ffma2(aA0y, wA[2*t+1], v0.y);
                    ffma2(aA1y, wA[2*t+1], v1.y);
                    ffma2(aB0y, wI[2*t+1], v0.y);
                    ffma2(aB1y, wI[2*t+1], v1.y);
                }
                #pragma unroll
                for (int t = 0; t < 16; t++) {        // h1 feeds wH
                    ulonglong2 v0 = h1b0[t], v1 = h1b1[t];
                    ffma2(aB0x, wH[2*t],   v0.x);
                    ffma2(aB1x, wH[2*t],   v1.x);
                    ffma2(aB0y, wH[2*t+1], v0.y);
                    ffma2(aB1y, wH[2*t+1], v1.y);
                }
            } else {
                #pragma unroll
                for (int t = 0; t < 16; t++) {        // h1 first (de-phased)
                    ulonglong2 v0 = h1b0[t], v1 = h1b1[t];
                    ffma2(aB0x, wH[2*t],   v0.x);
                    ffma2(aB1x, wH[2*t],   v1.x);
                    ffma2(aB0y, wH[2*t+1], v0.y);
                    ffma2(aB1y, wH[2*t+1], v1.y);
                }
                #pragma unroll
                for (int t = 0; t < 16; t++) {        // then h0
                    ulonglong2 v0 = h0b0[t], v1 = h0b1[t];
                    ffma2(aA0x, wA[2*t],   v0.x);
                    ffma2(aA1x, wA[2*t],   v1.x);
                    ffma2(aB0x, wI[2*t],   v0.x);
                    ffma2(aB1x, wI[2*t],   v1.x);
                    ffma2(aA0y, wA[2*t+1], v0.y);
                    ffma2(aA1y, wA[2*t+1], v1.y);
                    ffma2(aB0y, wI[2*t+1], v0.y);
                    ffma2(aB1y, wI[2*t+1], v1.y);
                }
            }

            float2 r0 = unpack2(aA0x), r1 = unpack2(aA0y);
            float2 r2 = unpack2(aA1x), r3 = unpack2(aA1y);
            float2 s0 = unpack2(aB0x), s1 = unpack2(aB0y);
            float2 s2 = unpack2(aB1x), s3 = unpack2(aB1y);
            float4 gv = make_float4((r0.x + r0.y) + (r1.x + r1.y),
                                    (r2.x + r2.y) + (r3.x + r3.y),
                                    (s0.x + s0.y) + (s1.x + s1.y),
                                    (s2.x + s2.y) + (s3.x + s3.y));
            *(float4*)&sh_s[w][l][0] = gv;        // {gA_b0, gA_b1, gB_b0, gB_b1}
        }
        __syncwarp();
        // ---- warp-local pointwise: lane -> (combo q, unit u) ----
        {
            const bool active = (q < 2) ? (k < TLEN) : (k >= 1);
            float g_i = sh_s[w][j     ][q];
            float g_f = sh_s[w][j +  8][q];
            float g_c = sh_s[w][j + 16][q];
            float g_o = sh_s[w][j + 24][q];
            float iv = fsigmoid(g_i), fv = fsigmoid(g_f), ov = fsigmoid(g_o);
            float cv = tanha(g_c);
            float cn = fmaf(fv, c, iv * cv);
            if (active) {
                c = cn;
                sh_h[ws][bq][hoff] = ov * tanha(c);
            }
        }
        __syncthreads();
    }

    // ---- FC head on final h1 (written at k=4000 -> slot 0) ----
    {
        const int e  = tid & 127;
        const int bb = tid >> 7;
        float acc = b_fc[e];
        const float* wr = W_fc + e * HID;
        const float* hv = &sh_h[0][bb][HID];
        #pragma unroll
        for (int t = 0; t < HID; t += 4) {
            acc = fmaf(wr[t],     hv[t],     acc);
            acc = fmaf(wr[t + 1], hv[t + 1], acc);
            acc = fmaf(wr[t + 2], hv[t + 2], acc);
            acc = fmaf(wr[t + 3], hv[t + 3], acc);
        }
        out[(size_t)(bbase + bb) * 128 + e] = acc;
    }
}

extern "C" void kernel_launch(void* const* d_in, const int* in_sizes, int n_in,
                              void* d_out, int out_size) {
    (void)in_sizes; (void)n_in; (void)out_size;
    lstm2_r13<<<128, NTHR>>>(
        (const float*)d_in[0],   // x
        (const float*)d_in[1],   // W_ih0
        (const float*)d_in[2],   // W_hh0
        (const float*)d_in[3],   // b_ih0
        (const float*)d_in[4],   // b_hh0
        (const float*)d_in[5],   // W_ih1
        (const float*)d_in[6],   // W_hh1
        (const float*)d_in[7],   // b_ih1
        (const float*)d_in[8],   // b_hh1
        (const float*)d_in[9],   // W_fc
        (const float*)d_in[10],  // b_fc
        (float*)d_out);
}

// round 14
// speedup vs baseline: 1.0691x; 1.0691x over previous
#include <cuda_runtime.h>

typedef unsigned long long ull;

#define TLEN 4000
#define HID  64
#define NTHR 256

__device__ __forceinline__ void ffma2(ull &d, ull a, ull b) {
    asm("fma.rn.f32x2 %0, %1, %2, %0;" : "+l"(d) : "l"(a), "l"(b));
}
__device__ __forceinline__ float2 unpack2(ull v) {
    float2 r;
    asm("mov.b64 {%0, %1}, %2;" : "=f"(r.x), "=f"(r.y) : "l"(v));
    return r;
}
__device__ __forceinline__ ull pack2(float x, float y) {
    ull r;
    asm("mov.b64 %0, {%1, %2};" : "=l"(r) : "f"(x), "f"(y));
    return r;
}
__device__ __forceinline__ float tanha(float x) {
    float r;
    asm("tanh.approx.f32 %0, %1;" : "=f"(r) : "f"(x));
    return r;
}
__device__ __forceinline__ float fsigmoid(float x) {
    // sigmoid(x) = 0.5*tanh(0.5x) + 0.5  (1 MUFU + FMA)
    return fmaf(tanha(0.5f * x), 0.5f, 0.5f);
}

__global__ void __launch_bounds__(NTHR, 1)
lstm2_r14(const float* __restrict__ x,
          const float* __restrict__ W_ih0,
          const float* __restrict__ W_hh0,
          const float* __restrict__ b_ih0,
          const float* __restrict__ b_hh0,
          const float* __restrict__ W_ih1,
          const float* __restrict__ W_hh1,
          const float* __restrict__ b_ih1,
          const float* __restrict__ b_hh1,
          const float* __restrict__ W_fc,
          const float* __restrict__ b_fc,
          float* __restrict__ out)
{
    __shared__ __align__(16) float sh_x[2 * TLEN];        // 32 KB staged input
    __shared__ __align__(16) float sh_h[2][2][2 * HID];   // dbl-buffered [h0|h1]
    __shared__ __align__(16) float sh_s[8][32][4];        // warp-local gate xchg

    const int tid   = threadIdx.x;
    const int w     = tid >> 5;
    const int l     = tid & 31;
    const int j     = l & 7;          // unit-local
    const int q     = l >> 3;         // gate index (i,f,g,o) AND pointwise combo
    const int u     = 8 * w + j;      // unit 0..63
    const int row   = q * HID + u;    // gate row this thread owns
    const int bbase = blockIdx.x * 2;

    // Stage x (two contiguous batch rows)
    {
        const float4* xg = (const float4*)(x + (size_t)bbase * TLEN);
        float4* xs = (float4*)sh_x;
        for (int i = tid; i < 2 * TLEN / 4; i += NTHR) xs[i] = xg[i];
    }
    ((float2*)sh_h)[tid] = make_float2(0.0f, 0.0f);   // zero both slots

    // Per-thread weight rows in registers (packed f32 pairs).
    ull wA[32], wI[32], wH[32];   // W_hh0 / W_ih1 / W_hh1 row `row`
    {
        const ulonglong2* p = (const ulonglong2*)(W_hh0 + row * HID);
        #pragma unroll
        for (int t = 0; t < 16; t++) { ulonglong2 v = p[t]; wA[2*t] = v.x; wA[2*t+1] = v.y; }
        p = (const ulonglong2*)(W_ih1 + row * HID);
        #pragma unroll
        for (int t = 0; t < 16; t++) { ulonglong2 v = p[t]; wI[2*t] = v.x; wI[2*t+1] = v.y; }
        p = (const ulonglong2*)(W_hh1 + row * HID);
        #pragma unroll
        for (int t = 0; t < 16; t++) { ulonglong2 v = p[t]; wH[2*t] = v.x; wH[2*t+1] = v.y; }
    }
    const float wx    = W_ih0[row];
    const float biasA = b_ih0[row] + b_hh0[row];
    const float biasB = b_ih1[row] + b_hh1[row];

    // Pointwise combo for this lane: q -> (layer Lq, batch bq), unit u.
    const int Lq = q >> 1;
    const int bq = q & 1;
    const int hoff = Lq * HID + u;
    float c = 0.0f;

    // Software-pipelined x-dependent gate-A init (hoisted across the barrier).
    float iA0 = fmaf(sh_x[0],    wx, biasA);
    float iA1 = fmaf(sh_x[TLEN], wx, biasA);

    __syncthreads();

    // Iter k: matvec gA(k) [layer0 step k] + gB(k-1) [layer1 step k-1],
    // warp-local pointwise -> h0(k), h1(k-1). ONE CTA barrier per step.
    for (int k = 0; k <= TLEN; ++k) {
        const int rs = (k + 1) & 1;   // read slot  (= writes of iter k-1)
        const int ws = k & 1;         // write slot
        // ---- fused matvec (gate-A init arrives precomputed) ----
        {
            ull aA0x = pack2(iA0, 0.0f), aA0y = pack2(0.0f, 0.0f);
            ull aA1x = pack2(iA1, 0.0f), aA1y = pack2(0.0f, 0.0f);
            ull aB0x = pack2(biasB, 0.0f), aB0y = pack2(0.0f, 0.0f);
            ull aB1x = aB0x,               aB1y = pack2(0.0f, 0.0f);

            const ulonglong2* h0b0 = (const ulonglong2*)&sh_h[rs][0][0];
            const ulonglong2* h0b1 = (const ulonglong2*)&sh_h[rs][1][0];
            const ulonglong2* h1b0 = (const ulonglong2*)&sh_h[rs][0][HID];
            const ulonglong2* h1b1 = (const ulonglong2*)&sh_h[rs][1][HID];

            #pragma unroll
            for (int t = 0; t < 16; t++) {        // h0 feeds wA and wI
                ulonglong2 v0 = h0b0[t], v1 = h0b1[t];
                ffma2(aA0x, wA[2*t],   v0.x);
                ffma2(aA1x, wA[2*t],   v1.x);
                ffma2(aB0x, wI[2*t],   v0.x);
                ffma2(aB1x, wI[2*t],   v1.x);
                ffma2(aA0y, wA[2*t+1], v0.y);
                ffma2(aA1y, wA[2*t+1], v1.y);
                ffma2(aB0y, wI[2*t+1], v0.y);
                ffma2(aB1y, wI[2*t+1], v1.y);
            }
            #pragma unroll
            for (int t = 0; t < 16; t++) {        // h1 feeds wH
                ulonglong2 v0 = h1b0[t], v1 = h1b1[t];
                ffma2(aB0x, wH[2*t],   v0.x);
                ffma2(aB1x, wH[2*t],   v1.x);
                ffma2(aB0y, wH[2*t+1], v0.y);
                ffma2(aB1y, wH[2*t+1], v1.y);
            }
            float2 r0 = unpack2(aA0x), r1 = unpack2(aA0y);
            float2 r2 = unpack2(aA1x), r3 = unpack2(aA1y);
            float2 s0 = unpack2(aB0x), s1 = unpack2(aB0y);
            float2 s2 = unpack2(aB1x), s3 = unpack2(aB1y);
            float4 gv = make_float4((r0.x + r0.y) + (r1.x + r1.y),
                                    (r2.x + r2.y) + (r3.x + r3.y),
                                    (s0.x + s0.y) + (s1.x + s1.y),
                                    (s2.x + s2.y) + (s3.x + s3.y));
            *(float4*)&sh_s[w][l][0] = gv;        // {gA_b0, gA_b1, gB_b0, gB_b1}
        }
        // ---- prefetch next step's x + gate-A init (hides under barrier) ----
        {
            const int kn = (k + 1 < TLEN) ? k + 1 : TLEN - 1;
            iA0 = fmaf(sh_x[kn],        wx, biasA);
            iA1 = fmaf(sh_x[TLEN + kn], wx, biasA);
        }
        __syncwarp();
        // ---- warp-local pointwise: lane -> (combo q, unit u) ----
        {
            const bool active = (q < 2) ? (k < TLEN) : (k >= 1);
            float g_i = sh_s[w][j     ][q];
            float g_f = sh_s[w][j +  8][q];
            float g_c = sh_s[w][j + 16][q];
            float g_o = sh_s[w][j + 24][q];
            float iv = fsigmoid(g_i), fv = fsigmoid(g_f), ov = fsigmoid(g_o);
            float cv = tanha(g_c);
            float cn = fmaf(fv, c, iv * cv);
            if (active) {
                c = cn;
                sh_h[ws][bq][hoff] = ov * tanha(c);
            }
        }
        __syncthreads();
    }

    // ---- FC head on final h1 (written at k=4000 -> slot 0) ----
    {
        const int e  = tid & 127;
        const int bb = tid >> 7;
        float acc = b_fc[e];
        const float* wr = W_fc + e * HID;
        const float* hv = &sh_h[0][bb][HID];
        #pragma unroll
        for (int t = 0; t < HID; t += 4) {
            acc = fmaf(wr[t],     hv[t],     acc);
            acc = fmaf(wr[t + 1], hv[t + 1], acc);
            acc = fmaf(wr[t + 2], hv[t + 2], acc);
            acc = fmaf(wr[t + 3], hv[t + 3], acc);
        }
        out[(size_t)(bbase + bb) * 128 + e] = acc;
    }
}

extern "C" void kernel_launch(void* const* d_in, const int* in_sizes, int n_in,
                              void* d_out, int out_size) {
    (void)in_sizes; (void)n_in; (void)out_size;
    lstm2_r14<<<128, NTHR>>>(
        (const float*)d_in[0],   // x
        (const float*)d_in[1],   // W_ih0
        (const float*)d_in[2],   // W_hh0
        (const float*)d_in[3],   // b_ih0
        (const float*)d_in[4],   // b_hh0
        (const float*)d_in[5],   // W_ih1
        (const float*)d_in[6],   // W_hh1
        (const float*)d_in[7],   // b_ih1
        (const float*)d_in[8],   // b_hh1
        (const float*)d_in[9],   // W_fc
        (const float*)d_in[10],  // b_fc
        (float*)d_out);
}

// round 15
// speedup vs baseline: 1.1333x; 1.0601x over previous
#include <cuda_runtime.h>

typedef unsigned long long ull;

#define TLEN 4000
#define HID  64
#define BT   2
#define NTHR 256

__device__ __forceinline__ void ffma2(ull &d, ull a, ull b) {
    asm("fma.rn.f32x2 %0, %1, %2, %0;" : "+l"(d) : "l"(a), "l"(b));
}
__device__ __forceinline__ float2 unpack2(ull v) {
    float2 r;
    asm("mov.b64 {%0, %1}, %2;" : "=f"(r.x), "=f"(r.y) : "l"(v));
    return r;
}
__device__ __forceinline__ ull pack2(float x, float y) {
    ull r;
    asm("mov.b64 %0, {%1, %2};" : "=l"(r) : "f"(x), "f"(y));
    return r;
}
__device__ __forceinline__ float hsum2(ull a, ull b) {
    ull s;
    asm("add.rn.f32x2 %0, %1, %2;" : "=l"(s) : "l"(a), "l"(b));
    float2 f = unpack2(s);
    return f.x + f.y;
}
__device__ __forceinline__ float tanha(float x) {
    float r;
    asm("tanh.approx.f32 %0, %1;" : "=f"(r) : "f"(x));
    return r;
}
__device__ __forceinline__ float fsigmoid(float x) {
    // sigmoid(x) = 0.5*tanh(0.5x) + 0.5  (1 MUFU + FMA)
    return fmaf(tanha(0.5f * x), 0.5f, 0.5f);
}

__global__ void __launch_bounds__(NTHR, 1)
lstm2_fin(const float* __restrict__ x,
          const float* __restrict__ W_ih0,
          const float* __restrict__ W_hh0,
          const float* __restrict__ b_ih0,
          const float* __restrict__ b_hh0,
          const float* __restrict__ W_ih1,
          const float* __restrict__ W_hh1,
          const float* __restrict__ b_ih1,
          const float* __restrict__ b_hh1,
          const float* __restrict__ W_fc,
          const float* __restrict__ b_fc,
          float* __restrict__ out)
{
    __shared__ __align__(16) float sh_x[BT * TLEN];       // 32 KB staged input
    __shared__ __align__(16) float sh_h[2][BT][2 * HID];  // dbl-buffered [h0|h1]
    __shared__ __align__(16) float sh_s[8][32][4];        // warp-local gate xchg

    const int tid   = threadIdx.x;
    const int w     = tid >> 5;
    const int l     = tid & 31;
    const int j     = l & 7;          // unit-local
    const int q     = l >> 3;         // gate index (i,f,g,o) AND pointwise combo
    const int u     = 8 * w + j;      // unit 0..63
    const int row   = q * HID + u;    // gate row this thread owns
    const int bbase = blockIdx.x * BT;

    // Stage x (two contiguous batch rows)
    {
        const float4* xg = (const float4*)(x + (size_t)bbase * TLEN);
        float4* xs = (float4*)sh_x;
        for (int i = tid; i < BT * TLEN / 4; i += NTHR) xs[i] = xg[i];
    }
    ((float2*)sh_h)[tid] = make_float2(0.0f, 0.0f);   // zero both slots (512 f)

    // Per-thread weight rows in registers (packed f32 pairs).
    ull wA[32], wI[32], wH[32];   // W_hh0 / W_ih1 / W_hh1 row `row`
    {
        const ulonglong2* p = (const ulonglong2*)(W_hh0 + row * HID);
        #pragma unroll
        for (int t = 0; t < 16; t++) { ulonglong2 v = p[t]; wA[2*t] = v.x; wA[2*t+1] = v.y; }
        p = (const ulonglong2*)(W_ih1 + row * HID);
        #pragma unroll
        for (int t = 0; t < 16; t++) { ulonglong2 v = p[t]; wI[2*t] = v.x; wI[2*t+1] = v.y; }
        p = (const ulonglong2*)(W_hh1 + row * HID);
        #pragma unroll
        for (int t = 0; t < 16; t++) { ulonglong2 v = p[t]; wH[2*t] = v.x; wH[2*t+1] = v.y; }
    }
    const float wx    = W_ih0[row];
    const float biasA = b_ih0[row] + b_hh0[row];
    const float biasB = b_ih1[row] + b_hh1[row];

    // Pointwise combo for this lane: q -> (layer Lq, batch bq), unit u.
    const int Lq = q >> 1;
    const int bq = q & 1;
    const int hoff = Lq * HID + u;
    float c = 0.0f;

    __syncthreads();

    // Iter k: matvec gA(k) [layer0 step k] + gB(k-1) [layer1 step k-1],
    // warp-local pointwise -> h0(k), h1(k-1). ONE CTA barrier per step.
    for (int k = 0; k <= TLEN; ++k) {
        const int rs = (k + 1) & 1;   // read slot  (= writes of iter k-1)
        const int ws = k & 1;         // write slot
        // ---- fused matvec ----
        {
            const int xk = (k < TLEN) ? k : TLEN - 1;
            const float xa = sh_x[xk];
            const float xb = sh_x[TLEN + xk];
            ull aA0x = pack2(fmaf(xa, wx, biasA), 0.0f), aA0y = pack2(0.0f, 0.0f);
            ull aA1x = pack2(fmaf(xb, wx, biasA), 0.0f), aA1y = pack2(0.0f, 0.0f);
            ull aB0x = pack2(biasB, 0.0f),               aB0y = pack2(0.0f, 0.0f);
            ull aB1x = aB0x,                             aB1y = pack2(0.0f, 0.0f);

            const ulonglong2* h0b0 = (const ulonglong2*)&sh_h[rs][0][0];
            const ulonglong2* h0b1 = (const ulonglong2*)&sh_h[rs][1][0];
            const ulonglong2* h1b0 = (const ulonglong2*)&sh_h[rs][0][HID];
            const ulonglong2* h1b1 = (const ulonglong2*)&sh_h[rs][1][HID];

            #pragma unroll
            for (int t = 0; t < 16; t++) {        // h0 feeds wA and wI
                ulonglong2 v0 = h0b0[t], v1 = h0b1[t];
                ffma2(aA0x, wA[2*t],   v0.x);
                ffma2(aA1x, wA[2*t],   v1.x);
                ffma2(aB0x, wI[2*t],   v0.x);
                ffma2(aB1x, wI[2*t],   v1.x);
                ffma2(aA0y, wA[2*t+1], v0.y);
                ffma2(aA1y, wA[2*t+1], v1.y);
                ffma2(aB0y, wI[2*t+1], v0.y);
                ffma2(aB1y, wI[2*t+1], v1.y);
            }
            #pragma unroll
            for (int t = 0; t < 16; t++) {        // h1 feeds wH
                ulonglong2 v0 = h1b0[t], v1 = h1b1[t];
                ffma2(aB0x, wH[2*t],   v0.x);
                ffma2(aB1x, wH[2*t],   v1.x);
                ffma2(aB0y, wH[2*t+1], v0.y);
                ffma2(aB1y, wH[2*t+1], v1.y);
            }
            float4 gv = make_float4(hsum2(aA0x, aA0y),
                                    hsum2(aA1x, aA1y),
                                    hsum2(aB0x, aB0y),
                                    hsum2(aB1x, aB1y));
            *(float4*)&sh_s[w][l][0] = gv;        // {gA_b0, gA_b1, gB_b0, gB_b1}
        }
        __syncwarp();
        // ---- warp-local pointwise: lane -> (combo q, unit u) ----
        {
            const bool active = (q < 2) ? (k < TLEN) : (k >= 1);
            float g_i = sh_s[w][j     ][q];
            float g_f = sh_s[w][j +  8][q];
            float g_c = sh_s[w][j + 16][q];
            float g_o = sh_s[w][j + 24][q];
            float iv = fsigmoid(g_i), fv = fsigmoid(g_f), ov = fsigmoid(g_o);
            float cv = tanha(g_c);
            float cn = fmaf(fv, c, iv * cv);
            if (active) {
                c = cn;
                sh_h[ws][bq][hoff] = ov * tanha(c);
            }
        }
        __syncthreads();
    }

    // ---- FC head on final h1 (written at k=4000 -> slot 0) ----
    {
        const int e  = tid & 127;
        const int bb = tid >> 7;
        float acc = b_fc[e];
        const float* wr = W_fc + e * HID;
        const float* hv = &sh_h[0][bb][HID];
        #pragma unroll
        for (int t = 0; t < HID; t += 4) {
            acc = fmaf(wr[t],     hv[t],     acc);
            acc = fmaf(wr[t + 1], hv[t + 1], acc);
            acc = fmaf(wr[t + 2], hv[t + 2], acc);
            acc = fmaf(wr[t + 3], hv[t + 3], acc);
        }
        out[(size_t)(bbase + bb) * 128 + e] = acc;
    }
}

extern "C" void kernel_launch(void* const* d_in, const int* in_sizes, int n_in,
                              void* d_out, int out_size) {
    (void)in_sizes; (void)n_in; (void)out_size;
    lstm2_fin<<<128, NTHR>>>(
        (const float*)d_in[0],   // x
        (const float*)d_in[1],   // W_ih0
        (const float*)d_in[2],   // W_hh0
        (const float*)d_in[3],   // b_ih0
        (const float*)d_in[4],   // b_hh0
        (const float*)d_in[5],   // W_ih1
        (const float*)d_in[6],   // W_hh1
        (const float*)d_in[7],   // b_ih1
        (const float*)d_in[8],   // b_hh1
        (const float*)d_in[9],   // W_fc
        (const float*)d_in[10],  // b_fc
        (float*)d_out);
}